// round 15
// baseline (speedup 1.0000x reference)
#include <cuda_runtime.h>
#include <cstdint>

#define NEXP 16
#define TTOT 8192
#define DM   1024
#define DF   2048
#define TPE  TTOT
#define BKC  32

#define AST  36
#define ASZ  (128*AST)              // 4608 floats (128-row A tiles)
#define BSTG 136
#define BSZG (BKC*BSTG)             // 4352 floats per B matrix
#define GU_STGF (ASZ + 2*BSZG)      // 13312 floats
#define GU_SMEM (3*GU_STGF*4)       // 159744 B

// dense down: M=64 tile (wave-packing), N=128
#define D1_ASZ  (64*AST)            // 2304 floats
#define D1_STGF (D1_ASZ + BSZG)     // 6656 floats
#define D1_SMEM (3*D1_STGF*4)       // 79872 B

#define BSTD 264
#define BSZD (BKC*BSTD)             // 8448
#define D2_STGF (ASZ + BSZD)        // 13056
#define D2_SMEM (3*D2_STGF*4)       // 156672 B

// ---------------- device scratch ----------------
__device__ int   g_cnt[NEXP];       // atomically built by router; re-zeroed by scan each run
__device__ int   g_len[NEXP];       // snapshot of counts (read by GEMM kernels)
__device__ int   g_off[NEXP];
__device__ int   g_tok[NEXP*TPE];
__device__ float g_wt [NEXP*TPE];
__device__ float g_Xr [(size_t)TTOT*DM];
__device__ float g_ACT[(size_t)3*TTOT*DF];   // dense rows [0,T), routed rows [T,3T)

// ---------------- helpers ----------------
__device__ __forceinline__ float tf32rnd(float v){
    uint32_t o; asm("cvt.rna.tf32.f32 %0, %1;" : "=r"(o) : "f"(v));
    return __uint_as_float(o);
}
__device__ __forceinline__ void cp_async16(uint32_t saddr, const void* g, int sz){
    asm volatile("cp.async.ca.shared.global [%0], [%1], 16, %2;\n" :: "r"(saddr), "l"(g), "r"(sz) : "memory");
}
__device__ __forceinline__ void cp_commit(){ asm volatile("cp.async.commit_group;\n" ::: "memory"); }
__device__ __forceinline__ void cp_wait1(){ asm volatile("cp.async.wait_group 1;\n" ::: "memory"); }
__device__ __forceinline__ void cp_wait0(){ asm volatile("cp.async.wait_group 0;\n" ::: "memory"); }
__device__ __forceinline__ uint32_t smem_u32(const void* p){
    uint32_t a;
    asm("{ .reg .u64 t; cvta.to.shared.u64 t, %1; cvt.u32.u64 %0, t; }" : "=r"(a) : "l"(p));
    return a;
}
__device__ __forceinline__ void mma_tf32(float c[4], uint32_t a0, uint32_t a1, uint32_t a2, uint32_t a3,
                                         uint32_t b0, uint32_t b1){
    asm volatile("mma.sync.aligned.m16n8k8.row.col.f32.tf32.tf32.f32 "
                 "{%0,%1,%2,%3}, {%4,%5,%6,%7}, {%8,%9}, {%0,%1,%2,%3};"
                 : "+f"(c[0]), "+f"(c[1]), "+f"(c[2]), "+f"(c[3])
                 : "r"(a0), "r"(a1), "r"(a2), "r"(a3), "r"(b0), "r"(b1));
}
__device__ __forceinline__ void red_add_v2(float* p, float v0, float v1){
    asm volatile("red.global.add.v2.f32 [%0], {%1, %2};" :: "l"(p), "f"(v0), "f"(v1) : "memory");
}

// ---------------- small kernels ----------------
// scan: snapshot counts -> g_len, prefix -> g_off, then zero g_cnt for the NEXT run.
__global__ void scan_kernel(){
    if (threadIdx.x == 0){
        int s = 0;
        #pragma unroll
        for (int e = 0; e < NEXP; e++){
            int c = g_cnt[e];
            g_len[e] = c;
            g_off[e] = s;
            s += c;
            g_cnt[e] = 0;
        }
    }
}

// router (also writes RNA-rounded x into g_Xr)
__global__ void router_kernel(const float* __restrict__ x, const float* __restrict__ Wr){
    int gw   = (blockIdx.x*blockDim.x + threadIdx.x) >> 5;
    int lane = threadIdx.x & 31;
    if (gw >= TTOT) return;
    const float* xr = x + (size_t)gw * DM;
    float*       xo = g_Xr + (size_t)gw * DM;
    float acc[NEXP];
    #pragma unroll
    for (int e = 0; e < NEXP; e++) acc[e] = 0.f;
    for (int d = lane; d < DM; d += 32){
        float xv = xr[d];
        xo[d] = tf32rnd(xv);
        const float4* wr = reinterpret_cast<const float4*>(Wr + d*NEXP);
        #pragma unroll
        for (int q = 0; q < 4; q++){
            float4 w = wr[q];
            acc[4*q+0] = fmaf(xv, w.x, acc[4*q+0]);
            acc[4*q+1] = fmaf(xv, w.y, acc[4*q+1]);
            acc[4*q+2] = fmaf(xv, w.z, acc[4*q+2]);
            acc[4*q+3] = fmaf(xv, w.w, acc[4*q+3]);
        }
    }
    #pragma unroll
    for (int e = 0; e < NEXP; e++){
        #pragma unroll
        for (int o = 16; o > 0; o >>= 1) acc[e] += __shfl_xor_sync(0xffffffffu, acc[e], o);
    }
    if (lane == 0){
        float mx = acc[0];
        #pragma unroll
        for (int e = 1; e < NEXP; e++) mx = fmaxf(mx, acc[e]);
        float p[NEXP];
        #pragma unroll
        for (int e = 0; e < NEXP; e++) p[e] = __expf(acc[e] - mx);
        float b1 = -1.f, b2 = -1.f; int i1 = 0, i2 = 0;
        #pragma unroll
        for (int e = 0; e < NEXP; e++){
            float v = p[e];
            if (v > b1){ b2 = b1; i2 = i1; b1 = v; i1 = e; }
            else if (v > b2){ b2 = v; i2 = e; }
        }
        float inv = 1.f / (b1 + b2);
        int p1 = atomicAdd(&g_cnt[i1], 1);
        g_tok[i1*TPE + p1] = gw;  g_wt[i1*TPE + p1] = b1 * inv;
        int p2 = atomicAdd(&g_cnt[i2], 1);
        g_tok[i2*TPE + p2] = gw;  g_wt[i2*TPE + p2] = b2 * inv;
    }
}

// ---------------- fused gate+up (tf32, 3-stage, ONE barrier/chunk) ----------------
__global__ void __launch_bounds__(256)
gu_kernel(const float* __restrict__ Wsg, const float* __restrict__ Wsu,
          const float* __restrict__ Weg, const float* __restrict__ Weu)
{
    constexpr int KT = DM / BKC;   // 32
    extern __shared__ float sm[];
    const uint32_t smb = smem_u32(sm);

    const int z = blockIdx.z;
    const bool routed = (z > 0);
    const int e = z - 1;
    const int M = routed ? g_len[e] : TTOT;
    const int m0 = blockIdx.y * 128;
    if (m0 >= M) return;
    const int n0 = blockIdx.x * 128;

    const float* Bg = routed ? Weg + (size_t)e*DM*DF : Wsg;   // [k][n]
    const float* Bu = routed ? Weu + (size_t)e*DM*DF : Wsu;
    const int abase = routed ? (TTOT + g_off[e]) : 0;

    const int tid = threadIdx.x;

    const int rb  = tid >> 3;
    const int cfa = (tid & 7) * 4;
    const float* arow[4]; int asz[4];
    #pragma unroll
    for (int p = 0; p < 4; p++){
        int gm = m0 + rb + p*32;
        if (routed){
            int ok = gm < M;
            arow[p] = g_Xr + (size_t)(ok ? g_tok[e*TPE + gm] : 0) * DM;
            asz[p]  = ok ? 16 : 0;
        } else { arow[p] = g_Xr + (size_t)gm * DM; asz[p] = 16; }
    }
    const int rb2 = tid >> 5;
    const int cfb = (tid & 31) * 4;

    auto load_chunk = [&](int kt, int s){
        const int k0 = kt * BKC;
        const uint32_t sb = smb + (uint32_t)(s * GU_STGF * 4);
        #pragma unroll
        for (int p = 0; p < 4; p++)
            cp_async16(sb + (uint32_t)(((rb + p*32)*AST + cfa)*4), arow[p] + k0 + cfa, asz[p]);
        #pragma unroll
        for (int p = 0; p < 4; p++){
            int r = rb2 + p*8;
            cp_async16(sb + (uint32_t)((ASZ + r*BSTG + cfb)*4),
                       Bg + (size_t)(k0 + r)*DF + n0 + cfb, 16);
            cp_async16(sb + (uint32_t)((ASZ + BSZG + r*BSTG + cfb)*4),
                       Bu + (size_t)(k0 + r)*DF + n0 + cfb, 16);
        }
    };
    auto round_B = [&](int s){
        float* B0 = sm + s*GU_STGF + ASZ;
        #pragma unroll
        for (int p = 0; p < 4; p++){
            float4* q1 = reinterpret_cast<float4*>(B0 + (rb2 + p*8)*BSTG + cfb);
            float4* q2 = reinterpret_cast<float4*>(B0 + BSZG + (rb2 + p*8)*BSTG + cfb);
            float4 v1 = *q1, v2 = *q2;
            v1.x=tf32rnd(v1.x); v1.y=tf32rnd(v1.y); v1.z=tf32rnd(v1.z); v1.w=tf32rnd(v1.w);
            v2.x=tf32rnd(v2.x); v2.y=tf32rnd(v2.y); v2.z=tf32rnd(v2.z); v2.w=tf32rnd(v2.w);
            *q1 = v1; *q2 = v2;
        }
    };

    const int wid = tid >> 5, lane = tid & 31;
    const int g = lane >> 2, t = lane & 3;
    const int wm = wid & 1;
    const int wn = wid >> 1;

    float cg[4][4][4], cu[4][4][4];
    #pragma unroll
    for (int i = 0; i < 4; i++)
        #pragma unroll
        for (int j = 0; j < 4; j++)
            #pragma unroll
            for (int q = 0; q < 4; q++){ cg[i][j][q] = 0.f; cu[i][j][q] = 0.f; }

    load_chunk(0, 0); cp_commit();
    load_chunk(1, 1); cp_commit();

    for (int kt = 0; kt < KT; kt++){
        const int s = kt % 3;
        if (kt + 1 < KT) cp_wait1(); else cp_wait0();
        round_B(s);
        __syncthreads();
        if (kt + 2 < KT){ load_chunk(kt + 2, (kt + 2) % 3); cp_commit(); }

        const float* As0 = sm + s*GU_STGF;
        const float* ab  = As0 + (wm*64 + g)*AST + t;
        const float* bgb = As0 + ASZ + t*BSTG + wn*32 + g;
        const float* bub = bgb + BSZG;

        #pragma unroll
        for (int kk = 0; kk < BKC; kk += 8){
            uint32_t a[4][4], bgf[4][2], buf[4][2];
            #pragma unroll
            for (int i = 0; i < 4; i++){
                a[i][0] = __float_as_uint(ab[(i*16    )*AST + kk    ]);
                a[i][1] = __float_as_uint(ab[(i*16 + 8)*AST + kk    ]);
                a[i][2] = __float_as_uint(ab[(i*16    )*AST + kk + 4]);
                a[i][3] = __float_as_uint(ab[(i*16 + 8)*AST + kk + 4]);
            }
            #pragma unroll
            for (int j = 0; j < 4; j++){
                bgf[j][0] = __float_as_uint(bgb[(kk    )*BSTG + j*8]);
                bgf[j][1] = __float_as_uint(bgb[(kk + 4)*BSTG + j*8]);
                buf[j][0] = __float_as_uint(bub[(kk    )*BSTG + j*8]);
                buf[j][1] = __float_as_uint(bub[(kk + 4)*BSTG + j*8]);
            }
            #pragma unroll
            for (int i = 0; i < 4; i++)
                #pragma unroll
                for (int j = 0; j < 4; j++){
                    mma_tf32(cg[i][j], a[i][0], a[i][1], a[i][2], a[i][3], bgf[j][0], bgf[j][1]);
                    mma_tf32(cu[i][j], a[i][0], a[i][1], a[i][2], a[i][3], buf[j][0], buf[j][1]);
                }
        }
    }

    #pragma unroll
    for (int i = 0; i < 4; i++){
        #pragma unroll
        for (int h = 0; h < 2; h++){
            const int gm = m0 + wm*64 + i*16 + g + h*8;
            if (routed && gm >= M) continue;
            float* drow = g_ACT + (size_t)(abase + gm)*DF;
            #pragma unroll
            for (int j = 0; j < 4; j++){
                const int cc = n0 + wn*32 + j*8 + 2*t;
                float g0 = cg[i][j][2*h], g1 = cg[i][j][2*h+1];
                float u0 = cu[i][j][2*h], u1 = cu[i][j][2*h+1];
                float o0 = tf32rnd(u0 * (g0 / (1.f + __expf(-g0))));
                float o1 = tf32rnd(u1 * (g1 / (1.f + __expf(-g1))));
                *reinterpret_cast<float2*>(drow + cc) = make_float2(o0, o1);
            }
        }
    }
}

// ---------------- dense down (CTA 64x128, warp 32x32, plain store) ----------------
__global__ void __launch_bounds__(256)
down_dense_kernel(const float* __restrict__ Wsd, float* __restrict__ Out)
{
    constexpr int KT = DF / BKC;   // 64
    extern __shared__ float sm[];
    const uint32_t smb = smem_u32(sm);

    const int m0 = blockIdx.y * 64;
    const int n0 = blockIdx.x * 128;
    const float* A = g_ACT;

    const int tid = threadIdx.x;
    const int rb  = tid >> 3;          // 0..31
    const int cfa = (tid & 7) * 4;
    const float* arow[2];
    #pragma unroll
    for (int p = 0; p < 2; p++) arow[p] = A + (size_t)(m0 + rb + p*32) * DF;
    const int rb2 = tid >> 5;
    const int cfb = (tid & 31) * 4;

    auto load_chunk = [&](int kt, int s){
        const int k0 = kt * BKC;
        const uint32_t sb = smb + (uint32_t)(s * D1_STGF * 4);
        #pragma unroll
        for (int p = 0; p < 2; p++)
            cp_async16(sb + (uint32_t)(((rb + p*32)*AST + cfa)*4), arow[p] + k0 + cfa, 16);
        #pragma unroll
        for (int p = 0; p < 4; p++){
            int r = rb2 + p*8;
            cp_async16(sb + (uint32_t)((D1_ASZ + r*BSTG + cfb)*4),
                       Wsd + (size_t)(k0 + r)*DM + n0 + cfb, 16);
        }
    };
    auto round_B = [&](int s){
        float* B0 = sm + s*D1_STGF + D1_ASZ;
        #pragma unroll
        for (int p = 0; p < 4; p++){
            float4* q1 = reinterpret_cast<float4*>(B0 + (rb2 + p*8)*BSTG + cfb);
            float4 v1 = *q1;
            v1.x=tf32rnd(v1.x); v1.y=tf32rnd(v1.y); v1.z=tf32rnd(v1.z); v1.w=tf32rnd(v1.w);
            *q1 = v1;
        }
    };

    const int wid = tid >> 5, lane = tid & 31;
    const int g = lane >> 2, t = lane & 3;
    const int wm = wid & 1;     // 2 x 32 rows
    const int wn = wid >> 1;    // 4 x 32 cols

    float c[2][4][4];
    #pragma unroll
    for (int i = 0; i < 2; i++)
        #pragma unroll
        for (int j = 0; j < 4; j++)
            #pragma unroll
            for (int q = 0; q < 4; q++) c[i][j][q] = 0.f;

    load_chunk(0, 0); cp_commit();
    load_chunk(1, 1); cp_commit();

    for (int kt = 0; kt < KT; kt++){
        const int s = kt % 3;
        if (kt + 1 < KT) cp_wait1(); else cp_wait0();
        round_B(s);
        __syncthreads();
        if (kt + 2 < KT){ load_chunk(kt + 2, (kt + 2) % 3); cp_commit(); }

        const float* As0 = sm + s*D1_STGF;
        const float* ab  = As0 + (wm*32 + g)*AST + t;
        const float* bb  = As0 + D1_ASZ + t*BSTG + wn*32 + g;

        #pragma unroll
        for (int kk = 0; kk < BKC; kk += 8){
            uint32_t a[2][4], b[4][2];
            #pragma unroll
            for (int i = 0; i < 2; i++){
                a[i][0] = __float_as_uint(ab[(i*16    )*AST + kk    ]);
                a[i][1] = __float_as_uint(ab[(i*16 + 8)*AST + kk    ]);
                a[i][2] = __float_as_uint(ab[(i*16    )*AST + kk + 4]);
                a[i][3] = __float_as_uint(ab[(i*16 + 8)*AST + kk + 4]);
            }
            #pragma unroll
            for (int j = 0; j < 4; j++){
                b[j][0] = __float_as_uint(bb[(kk    )*BSTG + j*8]);
                b[j][1] = __float_as_uint(bb[(kk + 4)*BSTG + j*8]);
            }
            #pragma unroll
            for (int i = 0; i < 2; i++)
                #pragma unroll
                for (int j = 0; j < 4; j++)
                    mma_tf32(c[i][j], a[i][0], a[i][1], a[i][2], a[i][3], b[j][0], b[j][1]);
        }
    }

    #pragma unroll
    for (int i = 0; i < 2; i++){
        #pragma unroll
        for (int h = 0; h < 2; h++){
            const int gm = m0 + wm*32 + i*16 + g + h*8;
            float* orow = Out + (size_t)gm*DM;
            #pragma unroll
            for (int j = 0; j < 4; j++){
                const int cc = n0 + wn*32 + j*8 + 2*t;
                *reinterpret_cast<float2*>(orow + cc) =
                    make_float2(c[i][j][2*h], c[i][j][2*h+1]);
            }
        }
    }
}

// ---------------- routed down (CTA 128x256, warp 64x64, red.v2 accumulate) ----------------
__global__ void __launch_bounds__(256)
down_routed_kernel(const float* __restrict__ Wed, float* __restrict__ Out)
{
    constexpr int KT = DF / BKC;   // 64
    extern __shared__ float sm[];
    const uint32_t smb = smem_u32(sm);

    const int e  = blockIdx.z;
    const int M  = g_len[e];
    const int m0 = blockIdx.y * 128;
    if (m0 >= M) return;
    const int n0 = blockIdx.x * 256;

    const float* B = Wed + (size_t)e*DF*DM;
    const float* A = g_ACT + (size_t)(TTOT + g_off[e]) * DF;

    const int tid = threadIdx.x;
    const int rb  = tid >> 3;
    const int cfa = (tid & 7) * 4;
    const float* arow[4]; int asz[4];
    #pragma unroll
    for (int p = 0; p < 4; p++){
        int gm = m0 + rb + p*32;
        int ok = gm < M;
        arow[p] = A + (size_t)(ok ? gm : 0) * DF;
        asz[p]  = ok ? 16 : 0;
    }
    const int rb2 = tid >> 5;
    const int cfb = (tid & 31) * 4;

    auto load_chunk = [&](int kt, int s){
        const int k0 = kt * BKC;
        const uint32_t sb = smb + (uint32_t)(s * D2_STGF * 4);
        #pragma unroll
        for (int p = 0; p < 4; p++)
            cp_async16(sb + (uint32_t)(((rb + p*32)*AST + cfa)*4), arow[p] + k0 + cfa, asz[p]);
        #pragma unroll
        for (int p = 0; p < 4; p++){
            int r = rb2 + p*8;
            cp_async16(sb + (uint32_t)((ASZ + r*BSTD + cfb)*4),
                       B + (size_t)(k0 + r)*DM + n0 + cfb, 16);
            cp_async16(sb + (uint32_t)((ASZ + r*BSTD + cfb + 128)*4),
                       B + (size_t)(k0 + r)*DM + n0 + cfb + 128, 16);
        }
    };
    auto round_B = [&](int s){
        float* B0 = sm + s*D2_STGF + ASZ;
        #pragma unroll
        for (int p = 0; p < 4; p++){
            float4* q1 = reinterpret_cast<float4*>(B0 + (rb2 + p*8)*BSTD + cfb);
            float4* q2 = reinterpret_cast<float4*>(B0 + (rb2 + p*8)*BSTD + cfb + 128);
            float4 v1 = *q1, v2 = *q2;
            v1.x=tf32rnd(v1.x); v1.y=tf32rnd(v1.y); v1.z=tf32rnd(v1.z); v1.w=tf32rnd(v1.w);
            v2.x=tf32rnd(v2.x); v2.y=tf32rnd(v2.y); v2.z=tf32rnd(v2.z); v2.w=tf32rnd(v2.w);
            *q1 = v1; *q2 = v2;
        }
    };

    const int wid = tid >> 5, lane = tid & 31;
    const int g = lane >> 2, t = lane & 3;
    const int wm = wid & 1;
    const int wn = wid >> 1;

    float c[4][8][4];
    #pragma unroll
    for (int i = 0; i < 4; i++)
        #pragma unroll
        for (int j = 0; j < 8; j++)
            #pragma unroll
            for (int q = 0; q < 4; q++) c[i][j][q] = 0.f;

    load_chunk(0, 0); cp_commit();
    load_chunk(1, 1); cp_commit();

    for (int kt = 0; kt < KT; kt++){
        const int s = kt % 3;
        if (kt + 1 < KT) cp_wait1(); else cp_wait0();
        round_B(s);
        __syncthreads();
        if (kt + 2 < KT){ load_chunk(kt + 2, (kt + 2) % 3); cp_commit(); }

        const float* As0 = sm + s*D2_STGF;
        const float* ab  = As0 + (wm*64 + g)*AST + t;
        const float* bb  = As0 + ASZ + t*BSTD + wn*64 + g;

        #pragma unroll
        for (int kk = 0; kk < BKC; kk += 8){
            uint32_t a[4][4], b[8][2];
            #pragma unroll
            for (int i = 0; i < 4; i++){
                a[i][0] = __float_as_uint(ab[(i*16    )*AST + kk    ]);
                a[i][1] = __float_as_uint(ab[(i*16 + 8)*AST + kk    ]);
                a[i][2] = __float_as_uint(ab[(i*16    )*AST + kk + 4]);
                a[i][3] = __float_as_uint(ab[(i*16 + 8)*AST + kk + 4]);
            }
            #pragma unroll
            for (int j = 0; j < 8; j++){
                b[j][0] = __float_as_uint(bb[(kk    )*BSTD + j*8]);
                b[j][1] = __float_as_uint(bb[(kk + 4)*BSTD + j*8]);
            }
            #pragma unroll
            for (int i = 0; i < 4; i++)
                #pragma unroll
                for (int j = 0; j < 8; j++)
                    mma_tf32(c[i][j], a[i][0], a[i][1], a[i][2], a[i][3], b[j][0], b[j][1]);
        }
    }

    #pragma unroll
    for (int i = 0; i < 4; i++){
        #pragma unroll
        for (int h = 0; h < 2; h++){
            const int gm = m0 + wm*64 + i*16 + g + h*8;
            if (gm >= M) continue;
            const int   tok = g_tok[e*TPE + gm];
            const float w   = g_wt [e*TPE + gm];
            float* orow = Out + (size_t)tok*DM;
            #pragma unroll
            for (int j = 0; j < 8; j++){
                const int cc = n0 + wn*64 + j*8 + 2*t;
                red_add_v2(orow + cc, w * c[i][j][2*h + 0], w * c[i][j][2*h + 1]);
            }
        }
    }
}

// ---------------- launch ----------------
extern "C" void kernel_launch(void* const* d_in, const int* in_sizes, int n_in,
                              void* d_out, int out_size)
{
    const float* x   = (const float*)d_in[0];
    const float* Wr  = (const float*)d_in[1];
    const float* Wsg = (const float*)d_in[2];
    const float* Wsu = (const float*)d_in[3];
    const float* Wsd = (const float*)d_in[4];
    const float* Weg = (const float*)d_in[5];
    const float* Weu = (const float*)d_in[6];
    const float* Wed = (const float*)d_in[7];
    float* out = (float*)d_out;

    cudaFuncSetAttribute(gu_kernel,          cudaFuncAttributeMaxDynamicSharedMemorySize, GU_SMEM);
    cudaFuncSetAttribute(down_dense_kernel,  cudaFuncAttributeMaxDynamicSharedMemorySize, D1_SMEM);
    cudaFuncSetAttribute(down_routed_kernel, cudaFuncAttributeMaxDynamicSharedMemorySize, D2_SMEM);

    // g_cnt is zero at module load and re-zeroed by scan_kernel each run -> deterministic replays
    router_kernel<<<TTOT/8, 256>>>(x, Wr);   // builds expert lists + RNA-rounded x
    scan_kernel<<<1, 32>>>();                // counts -> g_len/g_off, g_cnt -> 0

    dim3 blk(256);
    gu_kernel<<<dim3(DF/128, TTOT/128, NEXP+1), blk, GU_SMEM>>>(Wsg, Wsu, Weg, Weu);
    down_dense_kernel <<<dim3(DM/128, TTOT/64, 1),     blk, D1_SMEM>>>(Wsd, out);
    down_routed_kernel<<<dim3(DM/256, TPE/128, NEXP),  blk, D2_SMEM>>>(Wed, out);
}

// round 16
// speedup vs baseline: 1.0025x; 1.0025x over previous
#include <cuda_runtime.h>
#include <cstdint>

#define NEXP 16
#define TTOT 8192
#define DM   1024
#define DF   2048
#define TPE  TTOT
#define BKC  32

#define AST  36
#define ASZ  (128*AST)              // 4608 floats
#define BSTG 136
#define BSZG (BKC*BSTG)             // 4352 floats per B matrix
#define GU_STGF (ASZ + 2*BSZG)      // 13312 floats
#define GU_SMEM (3*GU_STGF*4)       // 159744 B

#define D1_STGF (ASZ + BSZG)        // dense down stage: 8960 floats
#define D1_SMEM (3*D1_STGF*4)       // 107520 B

#define BSTD 264
#define BSZD (BKC*BSTD)             // 8448
#define D2_STGF (ASZ + BSZD)        // 13056
#define D2_SMEM (3*D2_STGF*4)       // 156672 B

// ---------------- device scratch ----------------
__device__ int   g_cnt[NEXP];       // built by router; re-zeroed by scan each run
__device__ int   g_len[NEXP];       // snapshot of counts (read by GEMM kernels)
__device__ int   g_off[NEXP];
__device__ int   g_tok[NEXP*TPE];
__device__ float g_wt [NEXP*TPE];
__device__ float g_Xr [(size_t)TTOT*DM];
__device__ float g_ACT[(size_t)3*TTOT*DF];   // dense rows [0,T), routed rows [T,3T)

// ---------------- helpers ----------------
__device__ __forceinline__ float tf32rnd(float v){
    uint32_t o; asm("cvt.rna.tf32.f32 %0, %1;" : "=r"(o) : "f"(v));
    return __uint_as_float(o);
}
__device__ __forceinline__ void cp_async16(uint32_t saddr, const void* g, int sz){
    asm volatile("cp.async.ca.shared.global [%0], [%1], 16, %2;\n" :: "r"(saddr), "l"(g), "r"(sz) : "memory");
}
__device__ __forceinline__ void cp_commit(){ asm volatile("cp.async.commit_group;\n" ::: "memory"); }
__device__ __forceinline__ void cp_wait1(){ asm volatile("cp.async.wait_group 1;\n" ::: "memory"); }
__device__ __forceinline__ void cp_wait0(){ asm volatile("cp.async.wait_group 0;\n" ::: "memory"); }
__device__ __forceinline__ uint32_t smem_u32(const void* p){
    uint32_t a;
    asm("{ .reg .u64 t; cvta.to.shared.u64 t, %1; cvt.u32.u64 %0, t; }" : "=r"(a) : "l"(p));
    return a;
}
__device__ __forceinline__ void mma_tf32(float c[4], uint32_t a0, uint32_t a1, uint32_t a2, uint32_t a3,
                                         uint32_t b0, uint32_t b1){
    asm volatile("mma.sync.aligned.m16n8k8.row.col.f32.tf32.tf32.f32 "
                 "{%0,%1,%2,%3}, {%4,%5,%6,%7}, {%8,%9}, {%0,%1,%2,%3};"
                 : "+f"(c[0]), "+f"(c[1]), "+f"(c[2]), "+f"(c[3])
                 : "r"(a0), "r"(a1), "r"(a2), "r"(a3), "r"(b0), "r"(b1));
}
__device__ __forceinline__ void red_add_v2(float* p, float v0, float v1){
    asm volatile("red.global.add.v2.f32 [%0], {%1, %2};" :: "l"(p), "f"(v0), "f"(v1) : "memory");
}

// ---------------- small kernels ----------------
// scan: snapshot counts -> g_len, prefix -> g_off, zero g_cnt for next run
__global__ void scan_kernel(){
    if (threadIdx.x == 0){
        int s = 0;
        #pragma unroll
        for (int e = 0; e < NEXP; e++){
            int c = g_cnt[e];
            g_len[e] = c;
            g_off[e] = s;
            s += c;
            g_cnt[e] = 0;
        }
    }
}

// router (also writes RNA-rounded x into g_Xr)
__global__ void router_kernel(const float* __restrict__ x, const float* __restrict__ Wr){
    int gw   = (blockIdx.x*blockDim.x + threadIdx.x) >> 5;
    int lane = threadIdx.x & 31;
    if (gw >= TTOT) return;
    const float* xr = x + (size_t)gw * DM;
    float*       xo = g_Xr + (size_t)gw * DM;
    float acc[NEXP];
    #pragma unroll
    for (int e = 0; e < NEXP; e++) acc[e] = 0.f;
    for (int d = lane; d < DM; d += 32){
        float xv = xr[d];
        xo[d] = tf32rnd(xv);
        const float4* wr = reinterpret_cast<const float4*>(Wr + d*NEXP);
        #pragma unroll
        for (int q = 0; q < 4; q++){
            float4 w = wr[q];
            acc[4*q+0] = fmaf(xv, w.x, acc[4*q+0]);
            acc[4*q+1] = fmaf(xv, w.y, acc[4*q+1]);
            acc[4*q+2] = fmaf(xv, w.z, acc[4*q+2]);
            acc[4*q+3] = fmaf(xv, w.w, acc[4*q+3]);
        }
    }
    #pragma unroll
    for (int e = 0; e < NEXP; e++){
        #pragma unroll
        for (int o = 16; o > 0; o >>= 1) acc[e] += __shfl_xor_sync(0xffffffffu, acc[e], o);
    }
    if (lane == 0){
        float mx = acc[0];
        #pragma unroll
        for (int e = 1; e < NEXP; e++) mx = fmaxf(mx, acc[e]);
        float p[NEXP];
        #pragma unroll
        for (int e = 0; e < NEXP; e++) p[e] = __expf(acc[e] - mx);
        float b1 = -1.f, b2 = -1.f; int i1 = 0, i2 = 0;
        #pragma unroll
        for (int e = 0; e < NEXP; e++){
            float v = p[e];
            if (v > b1){ b2 = b1; i2 = i1; b1 = v; i1 = e; }
            else if (v > b2){ b2 = v; i2 = e; }
        }
        float inv = 1.f / (b1 + b2);
        int p1 = atomicAdd(&g_cnt[i1], 1);
        g_tok[i1*TPE + p1] = gw;  g_wt[i1*TPE + p1] = b1 * inv;
        int p2 = atomicAdd(&g_cnt[i2], 1);
        g_tok[i2*TPE + p2] = gw;  g_wt[i2*TPE + p2] = b2 * inv;
    }
}

// ---------------- fused gate+up (tf32, 3-stage, ONE barrier/chunk) ----------------
__global__ void __launch_bounds__(256)
gu_kernel(const float* __restrict__ Wsg, const float* __restrict__ Wsu,
          const float* __restrict__ Weg, const float* __restrict__ Weu)
{
    constexpr int KT = DM / BKC;   // 32
    extern __shared__ float sm[];
    const uint32_t smb = smem_u32(sm);

    const int z = blockIdx.z;
    const bool routed = (z > 0);
    const int e = z - 1;
    const int M = routed ? g_len[e] : TTOT;
    const int m0 = blockIdx.y * 128;
    if (m0 >= M) return;
    const int n0 = blockIdx.x * 128;

    const float* Bg = routed ? Weg + (size_t)e*DM*DF : Wsg;   // [k][n]
    const float* Bu = routed ? Weu + (size_t)e*DM*DF : Wsu;
    const int abase = routed ? (TTOT + g_off[e]) : 0;

    const int tid = threadIdx.x;

    const int rb  = tid >> 3;
    const int cfa = (tid & 7) * 4;
    const float* arow[4]; int asz[4];
    #pragma unroll
    for (int p = 0; p < 4; p++){
        int gm = m0 + rb + p*32;
        if (routed){
            int ok = gm < M;
            arow[p] = g_Xr + (size_t)(ok ? g_tok[e*TPE + gm] : 0) * DM;
            asz[p]  = ok ? 16 : 0;
        } else { arow[p] = g_Xr + (size_t)gm * DM; asz[p] = 16; }
    }
    const int rb2 = tid >> 5;
    const int cfb = (tid & 31) * 4;

    auto load_chunk = [&](int kt, int s){
        const int k0 = kt * BKC;
        const uint32_t sb = smb + (uint32_t)(s * GU_STGF * 4);
        #pragma unroll
        for (int p = 0; p < 4; p++)
            cp_async16(sb + (uint32_t)(((rb + p*32)*AST + cfa)*4), arow[p] + k0 + cfa, asz[p]);
        #pragma unroll
        for (int p = 0; p < 4; p++){
            int r = rb2 + p*8;
            cp_async16(sb + (uint32_t)((ASZ + r*BSTG + cfb)*4),
                       Bg + (size_t)(k0 + r)*DF + n0 + cfb, 16);
            cp_async16(sb + (uint32_t)((ASZ + BSZG + r*BSTG + cfb)*4),
                       Bu + (size_t)(k0 + r)*DF + n0 + cfb, 16);
        }
    };
    auto round_B = [&](int s){
        float* B0 = sm + s*GU_STGF + ASZ;
        #pragma unroll
        for (int p = 0; p < 4; p++){
            float4* q1 = reinterpret_cast<float4*>(B0 + (rb2 + p*8)*BSTG + cfb);
            float4* q2 = reinterpret_cast<float4*>(B0 + BSZG + (rb2 + p*8)*BSTG + cfb);
            float4 v1 = *q1, v2 = *q2;
            v1.x=tf32rnd(v1.x); v1.y=tf32rnd(v1.y); v1.z=tf32rnd(v1.z); v1.w=tf32rnd(v1.w);
            v2.x=tf32rnd(v2.x); v2.y=tf32rnd(v2.y); v2.z=tf32rnd(v2.z); v2.w=tf32rnd(v2.w);
            *q1 = v1; *q2 = v2;
        }
    };

    const int wid = tid >> 5, lane = tid & 31;
    const int g = lane >> 2, t = lane & 3;
    const int wm = wid & 1;
    const int wn = wid >> 1;

    float cg[4][4][4], cu[4][4][4];
    #pragma unroll
    for (int i = 0; i < 4; i++)
        #pragma unroll
        for (int j = 0; j < 4; j++)
            #pragma unroll
            for (int q = 0; q < 4; q++){ cg[i][j][q] = 0.f; cu[i][j][q] = 0.f; }

    load_chunk(0, 0); cp_commit();
    load_chunk(1, 1); cp_commit();

    for (int kt = 0; kt < KT; kt++){
        const int s = kt % 3;
        if (kt + 1 < KT) cp_wait1(); else cp_wait0();
        round_B(s);
        __syncthreads();
        if (kt + 2 < KT){ load_chunk(kt + 2, (kt + 2) % 3); cp_commit(); }

        const float* As0 = sm + s*GU_STGF;
        const float* ab  = As0 + (wm*64 + g)*AST + t;
        const float* bgb = As0 + ASZ + t*BSTG + wn*32 + g;
        const float* bub = bgb + BSZG;

        #pragma unroll
        for (int kk = 0; kk < BKC; kk += 8){
            uint32_t a[4][4], bgf[4][2], buf[4][2];
            #pragma unroll
            for (int i = 0; i < 4; i++){
                a[i][0] = __float_as_uint(ab[(i*16    )*AST + kk    ]);
                a[i][1] = __float_as_uint(ab[(i*16 + 8)*AST + kk    ]);
                a[i][2] = __float_as_uint(ab[(i*16    )*AST + kk + 4]);
                a[i][3] = __float_as_uint(ab[(i*16 + 8)*AST + kk + 4]);
            }
            #pragma unroll
            for (int j = 0; j < 4; j++){
                bgf[j][0] = __float_as_uint(bgb[(kk    )*BSTG + j*8]);
                bgf[j][1] = __float_as_uint(bgb[(kk + 4)*BSTG + j*8]);
                buf[j][0] = __float_as_uint(bub[(kk    )*BSTG + j*8]);
                buf[j][1] = __float_as_uint(bub[(kk + 4)*BSTG + j*8]);
            }
            #pragma unroll
            for (int i = 0; i < 4; i++)
                #pragma unroll
                for (int j = 0; j < 4; j++){
                    mma_tf32(cg[i][j], a[i][0], a[i][1], a[i][2], a[i][3], bgf[j][0], bgf[j][1]);
                    mma_tf32(cu[i][j], a[i][0], a[i][1], a[i][2], a[i][3], buf[j][0], buf[j][1]);
                }
        }
    }

    #pragma unroll
    for (int i = 0; i < 4; i++){
        #pragma unroll
        for (int h = 0; h < 2; h++){
            const int gm = m0 + wm*64 + i*16 + g + h*8;
            if (routed && gm >= M) continue;
            float* drow = g_ACT + (size_t)(abase + gm)*DF;
            #pragma unroll
            for (int j = 0; j < 4; j++){
                const int cc = n0 + wn*32 + j*8 + 2*t;
                float g0 = cg[i][j][2*h], g1 = cg[i][j][2*h+1];
                float u0 = cu[i][j][2*h], u1 = cu[i][j][2*h+1];
                float o0 = tf32rnd(u0 * (g0 / (1.f + __expf(-g0))));
                float o1 = tf32rnd(u1 * (g1 / (1.f + __expf(-g1))));
                *reinterpret_cast<float2*>(drow + cc) = make_float2(o0, o1);
            }
        }
    }
}

// ---------------- dense down (CTA 128x128, warp 64x32, plain store) ----------------
__global__ void __launch_bounds__(256)
down_dense_kernel(const float* __restrict__ Wsd, float* __restrict__ Out)
{
    constexpr int KT = DF / BKC;   // 64
    extern __shared__ float sm[];
    const uint32_t smb = smem_u32(sm);

    const int m0 = blockIdx.y * 128;
    const int n0 = blockIdx.x * 128;
    const float* A = g_ACT;

    const int tid = threadIdx.x;
    const int rb  = tid >> 3;
    const int cfa = (tid & 7) * 4;
    const float* arow[4];
    #pragma unroll
    for (int p = 0; p < 4; p++) arow[p] = A + (size_t)(m0 + rb + p*32) * DF;
    const int rb2 = tid >> 5;
    const int cfb = (tid & 31) * 4;

    auto load_chunk = [&](int kt, int s){
        const int k0 = kt * BKC;
        const uint32_t sb = smb + (uint32_t)(s * D1_STGF * 4);
        #pragma unroll
        for (int p = 0; p < 4; p++)
            cp_async16(sb + (uint32_t)(((rb + p*32)*AST + cfa)*4), arow[p] + k0 + cfa, 16);
        #pragma unroll
        for (int p = 0; p < 4; p++){
            int r = rb2 + p*8;
            cp_async16(sb + (uint32_t)((ASZ + r*BSTG + cfb)*4),
                       Wsd + (size_t)(k0 + r)*DM + n0 + cfb, 16);
        }
    };
    auto round_B = [&](int s){
        float* B0 = sm + s*D1_STGF + ASZ;
        #pragma unroll
        for (int p = 0; p < 4; p++){
            float4* q1 = reinterpret_cast<float4*>(B0 + (rb2 + p*8)*BSTG + cfb);
            float4 v1 = *q1;
            v1.x=tf32rnd(v1.x); v1.y=tf32rnd(v1.y); v1.z=tf32rnd(v1.z); v1.w=tf32rnd(v1.w);
            *q1 = v1;
        }
    };

    const int wid = tid >> 5, lane = tid & 31;
    const int g = lane >> 2, t = lane & 3;
    const int wm = wid & 1;
    const int wn = wid >> 1;

    float c[4][4][4];
    #pragma unroll
    for (int i = 0; i < 4; i++)
        #pragma unroll
        for (int j = 0; j < 4; j++)
            #pragma unroll
            for (int q = 0; q < 4; q++) c[i][j][q] = 0.f;

    load_chunk(0, 0); cp_commit();
    load_chunk(1, 1); cp_commit();

    for (int kt = 0; kt < KT; kt++){
        const int s = kt % 3;
        if (kt + 1 < KT) cp_wait1(); else cp_wait0();
        round_B(s);
        __syncthreads();
        if (kt + 2 < KT){ load_chunk(kt + 2, (kt + 2) % 3); cp_commit(); }

        const float* As0 = sm + s*D1_STGF;
        const float* ab  = As0 + (wm*64 + g)*AST + t;
        const float* bb  = As0 + ASZ + t*BSTG + wn*32 + g;

        #pragma unroll
        for (int kk = 0; kk < BKC; kk += 8){
            uint32_t a[4][4], b[4][2];
            #pragma unroll
            for (int i = 0; i < 4; i++){
                a[i][0] = __float_as_uint(ab[(i*16    )*AST + kk    ]);
                a[i][1] = __float_as_uint(ab[(i*16 + 8)*AST + kk    ]);
                a[i][2] = __float_as_uint(ab[(i*16    )*AST + kk + 4]);
                a[i][3] = __float_as_uint(ab[(i*16 + 8)*AST + kk + 4]);
            }
            #pragma unroll
            for (int j = 0; j < 4; j++){
                b[j][0] = __float_as_uint(bb[(kk    )*BSTG + j*8]);
                b[j][1] = __float_as_uint(bb[(kk + 4)*BSTG + j*8]);
            }
            #pragma unroll
            for (int i = 0; i < 4; i++)
                #pragma unroll
                for (int j = 0; j < 4; j++)
                    mma_tf32(c[i][j], a[i][0], a[i][1], a[i][2], a[i][3], b[j][0], b[j][1]);
        }
    }

    #pragma unroll
    for (int i = 0; i < 4; i++){
        #pragma unroll
        for (int h = 0; h < 2; h++){
            const int gm = m0 + wm*64 + i*16 + g + h*8;
            float* orow = Out + (size_t)gm*DM;
            #pragma unroll
            for (int j = 0; j < 4; j++){
                const int cc = n0 + wn*32 + j*8 + 2*t;
                *reinterpret_cast<float2*>(orow + cc) =
                    make_float2(c[i][j][2*h], c[i][j][2*h+1]);
            }
        }
    }
}

// ---------------- routed down (CTA 128x256, warp 64x64, red.v2 accumulate) ----------------
__global__ void __launch_bounds__(256)
down_routed_kernel(const float* __restrict__ Wed, float* __restrict__ Out)
{
    constexpr int KT = DF / BKC;   // 64
    extern __shared__ float sm[];
    const uint32_t smb = smem_u32(sm);

    const int e  = blockIdx.z;
    const int M  = g_len[e];
    const int m0 = blockIdx.y * 128;
    if (m0 >= M) return;
    const int n0 = blockIdx.x * 256;

    const float* B = Wed + (size_t)e*DF*DM;
    const float* A = g_ACT + (size_t)(TTOT + g_off[e]) * DF;

    const int tid = threadIdx.x;
    const int rb  = tid >> 3;
    const int cfa = (tid & 7) * 4;
    const float* arow[4]; int asz[4];
    #pragma unroll
    for (int p = 0; p < 4; p++){
        int gm = m0 + rb + p*32;
        int ok = gm < M;
        arow[p] = A + (size_t)(ok ? gm : 0) * DF;
        asz[p]  = ok ? 16 : 0;
    }
    const int rb2 = tid >> 5;
    const int cfb = (tid & 31) * 4;

    auto load_chunk = [&](int kt, int s){
        const int k0 = kt * BKC;
        const uint32_t sb = smb + (uint32_t)(s * D2_STGF * 4);
        #pragma unroll
        for (int p = 0; p < 4; p++)
            cp_async16(sb + (uint32_t)(((rb + p*32)*AST + cfa)*4), arow[p] + k0 + cfa, asz[p]);
        #pragma unroll
        for (int p = 0; p < 4; p++){
            int r = rb2 + p*8;
            cp_async16(sb + (uint32_t)((ASZ + r*BSTD + cfb)*4),
                       B + (size_t)(k0 + r)*DM + n0 + cfb, 16);
            cp_async16(sb + (uint32_t)((ASZ + r*BSTD + cfb + 128)*4),
                       B + (size_t)(k0 + r)*DM + n0 + cfb + 128, 16);
        }
    };
    auto round_B = [&](int s){
        float* B0 = sm + s*D2_STGF + ASZ;
        #pragma unroll
        for (int p = 0; p < 4; p++){
            float4* q1 = reinterpret_cast<float4*>(B0 + (rb2 + p*8)*BSTD + cfb);
            float4* q2 = reinterpret_cast<float4*>(B0 + (rb2 + p*8)*BSTD + cfb + 128);
            float4 v1 = *q1, v2 = *q2;
            v1.x=tf32rnd(v1.x); v1.y=tf32rnd(v1.y); v1.z=tf32rnd(v1.z); v1.w=tf32rnd(v1.w);
            v2.x=tf32rnd(v2.x); v2.y=tf32rnd(v2.y); v2.z=tf32rnd(v2.z); v2.w=tf32rnd(v2.w);
            *q1 = v1; *q2 = v2;
        }
    };

    const int wid = tid >> 5, lane = tid & 31;
    const int g = lane >> 2, t = lane & 3;
    const int wm = wid & 1;
    const int wn = wid >> 1;

    float c[4][8][4];
    #pragma unroll
    for (int i = 0; i < 4; i++)
        #pragma unroll
        for (int j = 0; j < 8; j++)
            #pragma unroll
            for (int q = 0; q < 4; q++) c[i][j][q] = 0.f;

    load_chunk(0, 0); cp_commit();
    load_chunk(1, 1); cp_commit();

    for (int kt = 0; kt < KT; kt++){
        const int s = kt % 3;
        if (kt + 1 < KT) cp_wait1(); else cp_wait0();
        round_B(s);
        __syncthreads();
        if (kt + 2 < KT){ load_chunk(kt + 2, (kt + 2) % 3); cp_commit(); }

        const float* As0 = sm + s*D2_STGF;
        const float* ab  = As0 + (wm*64 + g)*AST + t;
        const float* bb  = As0 + ASZ + t*BSTD + wn*64 + g;

        #pragma unroll
        for (int kk = 0; kk < BKC; kk += 8){
            uint32_t a[4][4], b[8][2];
            #pragma unroll
            for (int i = 0; i < 4; i++){
                a[i][0] = __float_as_uint(ab[(i*16    )*AST + kk    ]);
                a[i][1] = __float_as_uint(ab[(i*16 + 8)*AST + kk    ]);
                a[i][2] = __float_as_uint(ab[(i*16    )*AST + kk + 4]);
                a[i][3] = __float_as_uint(ab[(i*16 + 8)*AST + kk + 4]);
            }
            #pragma unroll
            for (int j = 0; j < 8; j++){
                b[j][0] = __float_as_uint(bb[(kk    )*BSTD + j*8]);
                b[j][1] = __float_as_uint(bb[(kk + 4)*BSTD + j*8]);
            }
            #pragma unroll
            for (int i = 0; i < 4; i++)
                #pragma unroll
                for (int j = 0; j < 8; j++)
                    mma_tf32(c[i][j], a[i][0], a[i][1], a[i][2], a[i][3], b[j][0], b[j][1]);
        }
    }

    #pragma unroll
    for (int i = 0; i < 4; i++){
        #pragma unroll
        for (int h = 0; h < 2; h++){
            const int gm = m0 + wm*64 + i*16 + g + h*8;
            if (gm >= M) continue;
            const int   tok = g_tok[e*TPE + gm];
            const float w   = g_wt [e*TPE + gm];
            float* orow = Out + (size_t)tok*DM;
            #pragma unroll
            for (int j = 0; j < 8; j++){
                const int cc = n0 + wn*64 + j*8 + 2*t;
                red_add_v2(orow + cc, w * c[i][j][2*h + 0], w * c[i][j][2*h + 1]);
            }
        }
    }
}

// ---------------- launch ----------------
extern "C" void kernel_launch(void* const* d_in, const int* in_sizes, int n_in,
                              void* d_out, int out_size)
{
    const float* x   = (const float*)d_in[0];
    const float* Wr  = (const float*)d_in[1];
    const float* Wsg = (const float*)d_in[2];
    const float* Wsu = (const float*)d_in[3];
    const float* Wsd = (const float*)d_in[4];
    const float* Weg = (const float*)d_in[5];
    const float* Weu = (const float*)d_in[6];
    const float* Wed = (const float*)d_in[7];
    float* out = (float*)d_out;

    cudaFuncSetAttribute(gu_kernel,          cudaFuncAttributeMaxDynamicSharedMemorySize, GU_SMEM);
    cudaFuncSetAttribute(down_dense_kernel,  cudaFuncAttributeMaxDynamicSharedMemorySize, D1_SMEM);
    cudaFuncSetAttribute(down_routed_kernel, cudaFuncAttributeMaxDynamicSharedMemorySize, D2_SMEM);

    // g_cnt is zero at module load and re-zeroed by scan_kernel each run -> deterministic replays
    router_kernel<<<TTOT/8, 256>>>(x, Wr);   // builds expert lists + RNA-rounded x
    scan_kernel<<<1, 32>>>();                // counts -> g_len/g_off, g_cnt -> 0

    dim3 blk(256);
    gu_kernel<<<dim3(DF/128, TTOT/128, NEXP+1), blk, GU_SMEM>>>(Wsg, Wsu, Weg, Weu);
    down_dense_kernel <<<dim3(DM/128, TTOT/128, 1),    blk, D1_SMEM>>>(Wsd, out);
    down_routed_kernel<<<dim3(DM/256, TPE/128, NEXP),  blk, D2_SMEM>>>(Wed, out);
}

// round 17
// speedup vs baseline: 1.0176x; 1.0150x over previous
#include <cuda_runtime.h>
#include <cstdint>

#define NEXP 16
#define TTOT 8192
#define DM   1024
#define DF   2048
#define TPE  TTOT
#define BKC  32

#define AST  36
#define ASZ  (128*AST)              // 4608 floats
#define BSTG 136
#define BSZG (BKC*BSTG)             // 4352 floats per B matrix
#define GU_STGF (ASZ + 2*BSZG)      // 13312 floats
#define GU_SMEM (3*GU_STGF*4)       // 159744 B

#define BSTD 264
#define BSZD (BKC*BSTD)             // 8448
#define DN_STGF (ASZ + BSZD)        // 13056
#define DN_SMEM (3*DN_STGF*4)       // 156672 B

// ---------------- device scratch ----------------
__device__ int   g_cnt[NEXP];       // built by router; re-zeroed by scan each run
__device__ int   g_len[NEXP];
__device__ int   g_off[NEXP];
__device__ int   g_tok[NEXP*TPE];
__device__ float g_wt [NEXP*TPE];
__device__ float g_Xr [(size_t)TTOT*DM];
__device__ float g_ACT[(size_t)3*TTOT*DF];   // dense rows [0,T), routed rows [T,3T)

// ---------------- helpers ----------------
__device__ __forceinline__ float tf32rnd(float v){
    uint32_t o; asm("cvt.rna.tf32.f32 %0, %1;" : "=r"(o) : "f"(v));
    return __uint_as_float(o);
}
__device__ __forceinline__ void cp_async16(uint32_t saddr, const void* g, int sz){
    asm volatile("cp.async.ca.shared.global [%0], [%1], 16, %2;\n" :: "r"(saddr), "l"(g), "r"(sz) : "memory");
}
__device__ __forceinline__ void cp_commit(){ asm volatile("cp.async.commit_group;\n" ::: "memory"); }
__device__ __forceinline__ void cp_wait1(){ asm volatile("cp.async.wait_group 1;\n" ::: "memory"); }
__device__ __forceinline__ void cp_wait0(){ asm volatile("cp.async.wait_group 0;\n" ::: "memory"); }
__device__ __forceinline__ uint32_t smem_u32(const void* p){
    uint32_t a;
    asm("{ .reg .u64 t; cvta.to.shared.u64 t, %1; cvt.u32.u64 %0, t; }" : "=r"(a) : "l"(p));
    return a;
}
__device__ __forceinline__ void mma_tf32(float c[4], uint32_t a0, uint32_t a1, uint32_t a2, uint32_t a3,
                                         uint32_t b0, uint32_t b1){
    asm volatile("mma.sync.aligned.m16n8k8.row.col.f32.tf32.tf32.f32 "
                 "{%0,%1,%2,%3}, {%4,%5,%6,%7}, {%8,%9}, {%0,%1,%2,%3};"
                 : "+f"(c[0]), "+f"(c[1]), "+f"(c[2]), "+f"(c[3])
                 : "r"(a0), "r"(a1), "r"(a2), "r"(a3), "r"(b0), "r"(b1));
}
__device__ __forceinline__ void red_add_v2(float* p, float v0, float v1){
    asm volatile("red.global.add.v2.f32 [%0], {%1, %2};" :: "l"(p), "f"(v0), "f"(v1) : "memory");
}

// ---------------- small kernels ----------------
__global__ void scan_kernel(){
    if (threadIdx.x == 0){
        int s = 0;
        #pragma unroll
        for (int e = 0; e < NEXP; e++){
            int c = g_cnt[e];
            g_len[e] = c;
            g_off[e] = s;
            s += c;
            g_cnt[e] = 0;
        }
    }
}

// router: routes tokens, RNA-rounds x into g_Xr, AND zeros the output row
// (out is red-add accumulated by the merged down kernel).
__global__ void router_kernel(const float* __restrict__ x, const float* __restrict__ Wr,
                              float* __restrict__ Out){
    int gw   = (blockIdx.x*blockDim.x + threadIdx.x) >> 5;
    int lane = threadIdx.x & 31;
    if (gw >= TTOT) return;
    const float* xr = x + (size_t)gw * DM;
    float*       xo = g_Xr + (size_t)gw * DM;
    // zero output row (coalesced float4 stores; overlaps with FMA latency below)
    float4* orow4 = reinterpret_cast<float4*>(Out + (size_t)gw * DM);
    #pragma unroll
    for (int q = 0; q < DM/4/32; q++)
        orow4[lane + q*32] = make_float4(0.f, 0.f, 0.f, 0.f);

    float acc[NEXP];
    #pragma unroll
    for (int e = 0; e < NEXP; e++) acc[e] = 0.f;
    for (int d = lane; d < DM; d += 32){
        float xv = xr[d];
        xo[d] = tf32rnd(xv);
        const float4* wr = reinterpret_cast<const float4*>(Wr + d*NEXP);
        #pragma unroll
        for (int q = 0; q < 4; q++){
            float4 w = wr[q];
            acc[4*q+0] = fmaf(xv, w.x, acc[4*q+0]);
            acc[4*q+1] = fmaf(xv, w.y, acc[4*q+1]);
            acc[4*q+2] = fmaf(xv, w.z, acc[4*q+2]);
            acc[4*q+3] = fmaf(xv, w.w, acc[4*q+3]);
        }
    }
    #pragma unroll
    for (int e = 0; e < NEXP; e++){
        #pragma unroll
        for (int o = 16; o > 0; o >>= 1) acc[e] += __shfl_xor_sync(0xffffffffu, acc[e], o);
    }
    if (lane == 0){
        float mx = acc[0];
        #pragma unroll
        for (int e = 1; e < NEXP; e++) mx = fmaxf(mx, acc[e]);
        float p[NEXP];
        #pragma unroll
        for (int e = 0; e < NEXP; e++) p[e] = __expf(acc[e] - mx);
        float b1 = -1.f, b2 = -1.f; int i1 = 0, i2 = 0;
        #pragma unroll
        for (int e = 0; e < NEXP; e++){
            float v = p[e];
            if (v > b1){ b2 = b1; i2 = i1; b1 = v; i1 = e; }
            else if (v > b2){ b2 = v; i2 = e; }
        }
        float inv = 1.f / (b1 + b2);
        int p1 = atomicAdd(&g_cnt[i1], 1);
        g_tok[i1*TPE + p1] = gw;  g_wt[i1*TPE + p1] = b1 * inv;
        int p2 = atomicAdd(&g_cnt[i2], 1);
        g_tok[i2*TPE + p2] = gw;  g_wt[i2*TPE + p2] = b2 * inv;
    }
}

// ---------------- fused gate+up (tf32, 3-stage, ONE barrier/chunk) ----------------
__global__ void __launch_bounds__(256)
gu_kernel(const float* __restrict__ Wsg, const float* __restrict__ Wsu,
          const float* __restrict__ Weg, const float* __restrict__ Weu)
{
    constexpr int KT = DM / BKC;   // 32
    extern __shared__ float sm[];
    const uint32_t smb = smem_u32(sm);

    const int z = blockIdx.z;
    const bool routed = (z > 0);
    const int e = z - 1;
    const int M = routed ? g_len[e] : TTOT;
    const int m0 = blockIdx.y * 128;
    if (m0 >= M) return;
    const int n0 = blockIdx.x * 128;

    const float* Bg = routed ? Weg + (size_t)e*DM*DF : Wsg;   // [k][n]
    const float* Bu = routed ? Weu + (size_t)e*DM*DF : Wsu;
    const int abase = routed ? (TTOT + g_off[e]) : 0;

    const int tid = threadIdx.x;

    const int rb  = tid >> 3;
    const int cfa = (tid & 7) * 4;
    const float* arow[4]; int asz[4];
    #pragma unroll
    for (int p = 0; p < 4; p++){
        int gm = m0 + rb + p*32;
        if (routed){
            int ok = gm < M;
            arow[p] = g_Xr + (size_t)(ok ? g_tok[e*TPE + gm] : 0) * DM;
            asz[p]  = ok ? 16 : 0;
        } else { arow[p] = g_Xr + (size_t)gm * DM; asz[p] = 16; }
    }
    const int rb2 = tid >> 5;
    const int cfb = (tid & 31) * 4;

    auto load_chunk = [&](int kt, int s){
        const int k0 = kt * BKC;
        const uint32_t sb = smb + (uint32_t)(s * GU_STGF * 4);
        #pragma unroll
        for (int p = 0; p < 4; p++)
            cp_async16(sb + (uint32_t)(((rb + p*32)*AST + cfa)*4), arow[p] + k0 + cfa, asz[p]);
        #pragma unroll
        for (int p = 0; p < 4; p++){
            int r = rb2 + p*8;
            cp_async16(sb + (uint32_t)((ASZ + r*BSTG + cfb)*4),
                       Bg + (size_t)(k0 + r)*DF + n0 + cfb, 16);
            cp_async16(sb + (uint32_t)((ASZ + BSZG + r*BSTG + cfb)*4),
                       Bu + (size_t)(k0 + r)*DF + n0 + cfb, 16);
        }
    };
    auto round_B = [&](int s){
        float* B0 = sm + s*GU_STGF + ASZ;
        #pragma unroll
        for (int p = 0; p < 4; p++){
            float4* q1 = reinterpret_cast<float4*>(B0 + (rb2 + p*8)*BSTG + cfb);
            float4* q2 = reinterpret_cast<float4*>(B0 + BSZG + (rb2 + p*8)*BSTG + cfb);
            float4 v1 = *q1, v2 = *q2;
            v1.x=tf32rnd(v1.x); v1.y=tf32rnd(v1.y); v1.z=tf32rnd(v1.z); v1.w=tf32rnd(v1.w);
            v2.x=tf32rnd(v2.x); v2.y=tf32rnd(v2.y); v2.z=tf32rnd(v2.z); v2.w=tf32rnd(v2.w);
            *q1 = v1; *q2 = v2;
        }
    };

    const int wid = tid >> 5, lane = tid & 31;
    const int g = lane >> 2, t = lane & 3;
    const int wm = wid & 1;
    const int wn = wid >> 1;

    float cg[4][4][4], cu[4][4][4];
    #pragma unroll
    for (int i = 0; i < 4; i++)
        #pragma unroll
        for (int j = 0; j < 4; j++)
            #pragma unroll
            for (int q = 0; q < 4; q++){ cg[i][j][q] = 0.f; cu[i][j][q] = 0.f; }

    load_chunk(0, 0); cp_commit();
    load_chunk(1, 1); cp_commit();

    for (int kt = 0; kt < KT; kt++){
        const int s = kt % 3;
        if (kt + 1 < KT) cp_wait1(); else cp_wait0();
        round_B(s);
        __syncthreads();
        if (kt + 2 < KT){ load_chunk(kt + 2, (kt + 2) % 3); cp_commit(); }

        const float* As0 = sm + s*GU_STGF;
        const float* ab  = As0 + (wm*64 + g)*AST + t;
        const float* bgb = As0 + ASZ + t*BSTG + wn*32 + g;
        const float* bub = bgb + BSZG;

        #pragma unroll
        for (int kk = 0; kk < BKC; kk += 8){
            uint32_t a[4][4], bgf[4][2], buf[4][2];
            #pragma unroll
            for (int i = 0; i < 4; i++){
                a[i][0] = __float_as_uint(ab[(i*16    )*AST + kk    ]);
                a[i][1] = __float_as_uint(ab[(i*16 + 8)*AST + kk    ]);
                a[i][2] = __float_as_uint(ab[(i*16    )*AST + kk + 4]);
                a[i][3] = __float_as_uint(ab[(i*16 + 8)*AST + kk + 4]);
            }
            #pragma unroll
            for (int j = 0; j < 4; j++){
                bgf[j][0] = __float_as_uint(bgb[(kk    )*BSTG + j*8]);
                bgf[j][1] = __float_as_uint(bgb[(kk + 4)*BSTG + j*8]);
                buf[j][0] = __float_as_uint(bub[(kk    )*BSTG + j*8]);
                buf[j][1] = __float_as_uint(bub[(kk + 4)*BSTG + j*8]);
            }
            #pragma unroll
            for (int i = 0; i < 4; i++)
                #pragma unroll
                for (int j = 0; j < 4; j++){
                    mma_tf32(cg[i][j], a[i][0], a[i][1], a[i][2], a[i][3], bgf[j][0], bgf[j][1]);
                    mma_tf32(cu[i][j], a[i][0], a[i][1], a[i][2], a[i][3], buf[j][0], buf[j][1]);
                }
        }
    }

    #pragma unroll
    for (int i = 0; i < 4; i++){
        #pragma unroll
        for (int h = 0; h < 2; h++){
            const int gm = m0 + wm*64 + i*16 + g + h*8;
            if (routed && gm >= M) continue;
            float* drow = g_ACT + (size_t)(abase + gm)*DF;
            #pragma unroll
            for (int j = 0; j < 4; j++){
                const int cc = n0 + wn*32 + j*8 + 2*t;
                float g0 = cg[i][j][2*h], g1 = cg[i][j][2*h+1];
                float u0 = cu[i][j][2*h], u1 = cu[i][j][2*h+1];
                float o0 = tf32rnd(u0 * (g0 / (1.f + __expf(-g0))));
                float o1 = tf32rnd(u1 * (g1 / (1.f + __expf(-g1))));
                *reinterpret_cast<float2*>(drow + cc) = make_float2(o0, o1);
            }
        }
    }
}

// ---------------- merged down (z=0 dense, z=1..16 routed; red.v2 into zeroed Out) --------
// CTA 128x256, warp tile 64x64 for both paths. Dense tiles dissolve into the big grid so
// early-exit routed CTAs backfill the dense wave tail (fixes down_dense quantization).
__global__ void __launch_bounds__(256)
down_kernel(const float* __restrict__ Wsd, const float* __restrict__ Wed, float* __restrict__ Out)
{
    constexpr int KT = DF / BKC;   // 64
    extern __shared__ float sm[];
    const uint32_t smb = smem_u32(sm);

    const int z = blockIdx.z;
    const bool routed = (z > 0);
    const int e = z - 1;
    const int M  = routed ? g_len[e] : TTOT;
    const int m0 = blockIdx.y * 128;
    if (m0 >= M) return;
    const int n0 = blockIdx.x * 256;

    const float* B = routed ? Wed + (size_t)e*DF*DM : Wsd;    // [k][n]
    const float* A = g_ACT + (size_t)(routed ? (TTOT + g_off[e]) : 0) * DF;

    const int tid = threadIdx.x;
    const int rb  = tid >> 3;
    const int cfa = (tid & 7) * 4;
    const float* arow[4]; int asz[4];
    #pragma unroll
    for (int p = 0; p < 4; p++){
        int gm = m0 + rb + p*32;
        int ok = (!routed) || (gm < M);
        arow[p] = A + (size_t)(ok ? gm : 0) * DF;
        asz[p]  = ok ? 16 : 0;
    }
    const int rb2 = tid >> 5;
    const int cfb = (tid & 31) * 4;

    auto load_chunk = [&](int kt, int s){
        const int k0 = kt * BKC;
        const uint32_t sb = smb + (uint32_t)(s * DN_STGF * 4);
        #pragma unroll
        for (int p = 0; p < 4; p++)
            cp_async16(sb + (uint32_t)(((rb + p*32)*AST + cfa)*4), arow[p] + k0 + cfa, asz[p]);
        #pragma unroll
        for (int p = 0; p < 4; p++){
            int r = rb2 + p*8;
            cp_async16(sb + (uint32_t)((ASZ + r*BSTD + cfb)*4),
                       B + (size_t)(k0 + r)*DM + n0 + cfb, 16);
            cp_async16(sb + (uint32_t)((ASZ + r*BSTD + cfb + 128)*4),
                       B + (size_t)(k0 + r)*DM + n0 + cfb + 128, 16);
        }
    };
    auto round_B = [&](int s){
        float* B0 = sm + s*DN_STGF + ASZ;
        #pragma unroll
        for (int p = 0; p < 4; p++){
            float4* q1 = reinterpret_cast<float4*>(B0 + (rb2 + p*8)*BSTD + cfb);
            float4* q2 = reinterpret_cast<float4*>(B0 + (rb2 + p*8)*BSTD + cfb + 128);
            float4 v1 = *q1, v2 = *q2;
            v1.x=tf32rnd(v1.x); v1.y=tf32rnd(v1.y); v1.z=tf32rnd(v1.z); v1.w=tf32rnd(v1.w);
            v2.x=tf32rnd(v2.x); v2.y=tf32rnd(v2.y); v2.z=tf32rnd(v2.z); v2.w=tf32rnd(v2.w);
            *q1 = v1; *q2 = v2;
        }
    };

    const int wid = tid >> 5, lane = tid & 31;
    const int g = lane >> 2, t = lane & 3;
    const int wm = wid & 1;
    const int wn = wid >> 1;

    float c[4][8][4];
    #pragma unroll
    for (int i = 0; i < 4; i++)
        #pragma unroll
        for (int j = 0; j < 8; j++)
            #pragma unroll
            for (int q = 0; q < 4; q++) c[i][j][q] = 0.f;

    load_chunk(0, 0); cp_commit();
    load_chunk(1, 1); cp_commit();

    for (int kt = 0; kt < KT; kt++){
        const int s = kt % 3;
        if (kt + 1 < KT) cp_wait1(); else cp_wait0();
        round_B(s);
        __syncthreads();
        if (kt + 2 < KT){ load_chunk(kt + 2, (kt + 2) % 3); cp_commit(); }

        const float* As0 = sm + s*DN_STGF;
        const float* ab  = As0 + (wm*64 + g)*AST + t;
        const float* bb  = As0 + ASZ + t*BSTD + wn*64 + g;

        #pragma unroll
        for (int kk = 0; kk < BKC; kk += 8){
            uint32_t a[4][4], b[8][2];
            #pragma unroll
            for (int i = 0; i < 4; i++){
                a[i][0] = __float_as_uint(ab[(i*16    )*AST + kk    ]);
                a[i][1] = __float_as_uint(ab[(i*16 + 8)*AST + kk    ]);
                a[i][2] = __float_as_uint(ab[(i*16    )*AST + kk + 4]);
                a[i][3] = __float_as_uint(ab[(i*16 + 8)*AST + kk + 4]);
            }
            #pragma unroll
            for (int j = 0; j < 8; j++){
                b[j][0] = __float_as_uint(bb[(kk    )*BSTD + j*8]);
                b[j][1] = __float_as_uint(bb[(kk + 4)*BSTD + j*8]);
            }
            #pragma unroll
            for (int i = 0; i < 4; i++)
                #pragma unroll
                for (int j = 0; j < 8; j++)
                    mma_tf32(c[i][j], a[i][0], a[i][1], a[i][2], a[i][3], b[j][0], b[j][1]);
        }
    }

    #pragma unroll
    for (int i = 0; i < 4; i++){
        #pragma unroll
        for (int h = 0; h < 2; h++){
            const int gm = m0 + wm*64 + i*16 + g + h*8;
            if (routed && gm >= M) continue;
            int tok = gm; float w = 1.f;
            if (routed){ tok = g_tok[e*TPE + gm]; w = g_wt[e*TPE + gm]; }
            float* orow = Out + (size_t)tok*DM;
            #pragma unroll
            for (int j = 0; j < 8; j++){
                const int cc = n0 + wn*64 + j*8 + 2*t;
                red_add_v2(orow + cc, w * c[i][j][2*h + 0], w * c[i][j][2*h + 1]);
            }
        }
    }
}

// ---------------- launch ----------------
extern "C" void kernel_launch(void* const* d_in, const int* in_sizes, int n_in,
                              void* d_out, int out_size)
{
    const float* x   = (const float*)d_in[0];
    const float* Wr  = (const float*)d_in[1];
    const float* Wsg = (const float*)d_in[2];
    const float* Wsu = (const float*)d_in[3];
    const float* Wsd = (const float*)d_in[4];
    const float* Weg = (const float*)d_in[5];
    const float* Weu = (const float*)d_in[6];
    const float* Wed = (const float*)d_in[7];
    float* out = (float*)d_out;

    cudaFuncSetAttribute(gu_kernel,   cudaFuncAttributeMaxDynamicSharedMemorySize, GU_SMEM);
    cudaFuncSetAttribute(down_kernel, cudaFuncAttributeMaxDynamicSharedMemorySize, DN_SMEM);

    // router zeros Out, routes tokens, and RNA-rounds x; scan snapshots + resets counts
    router_kernel<<<TTOT/8, 256>>>(x, Wr, out);
    scan_kernel<<<1, 32>>>();

    dim3 blk(256);
    gu_kernel  <<<dim3(DF/128, TTOT/128, NEXP+1), blk, GU_SMEM>>>(Wsg, Wsu, Weg, Weu);
    down_kernel<<<dim3(DM/256, TTOT/128, NEXP+1), blk, DN_SMEM>>>(Wsd, Wed, out);
}